// round 1
// baseline (speedup 1.0000x reference)
#include <cuda_runtime.h>
#include <cuda_bf16.h>

// SoftmaxPooling: y[g] = sum_{i in g} exp(Xa[i]) * X[i] / sum_{i in g} exp(Xa[i])
// graph_idx is sorted ascending -> segments are contiguous node ranges.
// One CTA per graph: binary-search [start,end), stream rows once, no atomics.

#define D 128

__global__ __launch_bounds__(D) void softmax_pool_kernel(
    const float* __restrict__ X,
    const float* __restrict__ Xatt,
    const int*   __restrict__ gidx,
    float*       __restrict__ out,
    int n_nodes, int n_graphs)
{
    const int g = blockIdx.x;
    const int d = threadIdx.x;

    __shared__ int s_bounds[2];

    // threads 0 and 1 each do one lower_bound over the sorted gidx array
    if (d < 2) {
        const int target = g + d;        // d==0 -> start (first idx >= g), d==1 -> end (first idx >= g+1)
        int lo = 0, hi = n_nodes;
        while (lo < hi) {
            int mid = (lo + hi) >> 1;
            if (gidx[mid] < target) lo = mid + 1;
            else                    hi = mid;
        }
        s_bounds[d] = lo;
    }
    __syncthreads();

    const int start = s_bounds[0];
    const int end   = s_bounds[1];

    // split accumulators to break the FADD dependency chain and batch LDGs
    float acc_a0 = 0.f, acc_a1 = 0.f, acc_a2 = 0.f, acc_a3 = 0.f;
    float acc_w0 = 0.f, acc_w1 = 0.f, acc_w2 = 0.f, acc_w3 = 0.f;

    int i = start;
    for (; i + 4 <= end; i += 4) {
        // front-batch the 8 loads (MLP)
        const long long b0 = (long long)(i + 0) * D + d;
        const long long b1 = (long long)(i + 1) * D + d;
        const long long b2 = (long long)(i + 2) * D + d;
        const long long b3 = (long long)(i + 3) * D + d;
        float xa0 = Xatt[b0], xa1 = Xatt[b1], xa2 = Xatt[b2], xa3 = Xatt[b3];
        float x0  = X[b0],    x1  = X[b1],    x2  = X[b2],    x3  = X[b3];
        float a0 = __expf(xa0);
        float a1 = __expf(xa1);
        float a2 = __expf(xa2);
        float a3 = __expf(xa3);
        acc_a0 += a0; acc_w0 = fmaf(a0, x0, acc_w0);
        acc_a1 += a1; acc_w1 = fmaf(a1, x1, acc_w1);
        acc_a2 += a2; acc_w2 = fmaf(a2, x2, acc_w2);
        acc_a3 += a3; acc_w3 = fmaf(a3, x3, acc_w3);
    }
    for (; i < end; ++i) {
        const long long b = (long long)i * D + d;
        float a = __expf(Xatt[b]);
        acc_a0 += a;
        acc_w0 = fmaf(a, X[b], acc_w0);
    }

    const float acc_a = (acc_a0 + acc_a1) + (acc_a2 + acc_a3);
    const float acc_w = (acc_w0 + acc_w1) + (acc_w2 + acc_w3);

    out[(long long)g * D + d] = acc_w / acc_a;
}

extern "C" void kernel_launch(void* const* d_in, const int* in_sizes, int n_in,
                              void* d_out, int out_size)
{
    const float* X    = (const float*)d_in[0];
    const float* Xatt = (const float*)d_in[1];
    const int*   gidx = (const int*)d_in[2];
    // d_in[3] = n (only its length matters)

    const int n_nodes  = in_sizes[2];            // graph_idx element count
    const int n_graphs = in_sizes[3];            // length of n
    (void)n_in;
    (void)out_size;

    softmax_pool_kernel<<<n_graphs, D>>>(X, Xatt, gidx, (float*)d_out,
                                         n_nodes, n_graphs);
}

// round 2
// speedup vs baseline: 1.1891x; 1.1891x over previous
#include <cuda_runtime.h>
#include <cuda_bf16.h>

// SoftmaxPooling: y[g] = sum_{i in g} exp(Xa[i]) * X[i] / sum_{i in g} exp(Xa[i])
// graph_idx sorted ascending -> segments are contiguous node ranges.
// Pass 1: boundary kernel writes seg_start[g] (first node index with gidx >= g).
// Pass 2: one CTA per graph streams its rows once with float4 loads; no atomics.

#define D 128
#define MAX_GRAPHS (4 * 1024 * 1024)

__device__ int g_seg_start[MAX_GRAPHS + 1];

__global__ void boundaries_kernel(const int* __restrict__ gidx,
                                  int n_nodes, int n_graphs)
{
    int i = blockIdx.x * blockDim.x + threadIdx.x;   // i in [0, n_nodes]
    if (i > n_nodes) return;
    int cur = (i < n_nodes) ? gidx[i] : n_graphs;
    int prv = (i > 0) ? gidx[i - 1] : -1;
    // seg_start[g] = i  for all g in (prv, cur]  (clamped to [0, n_graphs])
    if (cur > n_graphs) cur = n_graphs;
    for (int g = prv + 1; g <= cur; ++g)
        g_seg_start[g] = i;
}

__global__ __launch_bounds__(D) void softmax_pool_kernel(
    const float* __restrict__ X,
    const float* __restrict__ Xatt,
    float*       __restrict__ out)
{
    const int g = blockIdx.x;
    const int t = threadIdx.x;
    const int w = t >> 5;          // warp 0..3
    const int l = t & 31;          // lane -> columns [4l, 4l+4)

    const int start = g_seg_start[g];
    const int end   = g_seg_start[g + 1];

    float4 aa0 = {0.f,0.f,0.f,0.f}, ww0 = {0.f,0.f,0.f,0.f};
    float4 aa1 = {0.f,0.f,0.f,0.f}, ww1 = {0.f,0.f,0.f,0.f};

    int i = start + w;
    // unroll 2: rows i and i+4
    for (; i + 4 < end; i += 8) {
        const float4* pxa0 = (const float4*)(Xatt + (size_t)i * D) + l;
        const float4* px0  = (const float4*)(X    + (size_t)i * D) + l;
        const float4* pxa1 = (const float4*)(Xatt + (size_t)(i + 4) * D) + l;
        const float4* px1  = (const float4*)(X    + (size_t)(i + 4) * D) + l;
        float4 xa0 = __ldcs(pxa0);
        float4 x0  = __ldcs(px0);
        float4 xa1 = __ldcs(pxa1);
        float4 x1  = __ldcs(px1);

        float4 a0, a1;
        a0.x = __expf(xa0.x); a0.y = __expf(xa0.y); a0.z = __expf(xa0.z); a0.w = __expf(xa0.w);
        a1.x = __expf(xa1.x); a1.y = __expf(xa1.y); a1.z = __expf(xa1.z); a1.w = __expf(xa1.w);

        aa0.x += a0.x; aa0.y += a0.y; aa0.z += a0.z; aa0.w += a0.w;
        ww0.x = fmaf(a0.x, x0.x, ww0.x); ww0.y = fmaf(a0.y, x0.y, ww0.y);
        ww0.z = fmaf(a0.z, x0.z, ww0.z); ww0.w = fmaf(a0.w, x0.w, ww0.w);

        aa1.x += a1.x; aa1.y += a1.y; aa1.z += a1.z; aa1.w += a1.w;
        ww1.x = fmaf(a1.x, x1.x, ww1.x); ww1.y = fmaf(a1.y, x1.y, ww1.y);
        ww1.z = fmaf(a1.z, x1.z, ww1.z); ww1.w = fmaf(a1.w, x1.w, ww1.w);
    }
    for (; i < end; i += 4) {
        const float4* pxa = (const float4*)(Xatt + (size_t)i * D) + l;
        const float4* px  = (const float4*)(X    + (size_t)i * D) + l;
        float4 xa = __ldcs(pxa);
        float4 x  = __ldcs(px);
        float4 a;
        a.x = __expf(xa.x); a.y = __expf(xa.y); a.z = __expf(xa.z); a.w = __expf(xa.w);
        aa0.x += a.x; aa0.y += a.y; aa0.z += a.z; aa0.w += a.w;
        ww0.x = fmaf(a.x, x.x, ww0.x); ww0.y = fmaf(a.y, x.y, ww0.y);
        ww0.z = fmaf(a.z, x.z, ww0.z); ww0.w = fmaf(a.w, x.w, ww0.w);
    }

    aa0.x += aa1.x; aa0.y += aa1.y; aa0.z += aa1.z; aa0.w += aa1.w;
    ww0.x += ww1.x; ww0.y += ww1.y; ww0.z += ww1.z; ww0.w += ww1.w;

    // cross-warp reduction: 4 warps hold partials for the same 4 columns per lane
    __shared__ float4 s_a[4][32];
    __shared__ float4 s_w[4][32];
    s_a[w][l] = aa0;
    s_w[w][l] = ww0;
    __syncthreads();

    if (t < 32) {
        float4 A = s_a[0][t], W = s_w[0][t];
        #pragma unroll
        for (int k = 1; k < 4; ++k) {
            float4 a = s_a[k][t], wv = s_w[k][t];
            A.x += a.x; A.y += a.y; A.z += a.z; A.w += a.w;
            W.x += wv.x; W.y += wv.y; W.z += wv.z; W.w += wv.w;
        }
        float4 r;
        r.x = W.x / A.x; r.y = W.y / A.y; r.z = W.z / A.z; r.w = W.w / A.w;
        ((float4*)(out + (size_t)g * D))[t] = r;
    }
}

extern "C" void kernel_launch(void* const* d_in, const int* in_sizes, int n_in,
                              void* d_out, int out_size)
{
    const float* X    = (const float*)d_in[0];
    const float* Xatt = (const float*)d_in[1];
    const int*   gidx = (const int*)d_in[2];

    const int n_nodes  = in_sizes[2];
    const int n_graphs = in_sizes[3];
    (void)n_in; (void)out_size;

    int bthreads = 256;
    int bblocks  = (n_nodes + 1 + bthreads - 1) / bthreads;
    boundaries_kernel<<<bblocks, bthreads>>>(gidx, n_nodes, n_graphs);

    softmax_pool_kernel<<<n_graphs, D>>>(X, Xatt, (float*)d_out);
}